// round 13
// baseline (speedup 1.0000x reference)
#include <cuda_runtime.h>
#include <cuda_bf16.h>
#include <math.h>
#include <stdint.h>

// ---------------- problem constants ----------------
#define BB      2
#define LLEN    2048
#define DMODEL  1024
#define DINNER  2048
#define DSTATE  16
#define DTRANK  64
#define NVOCAB  32000
#define NVPAD   32256                 // 63 x 512
#define MTOT    (BB * LLEN)           // 4096 rows
#define XDBL_W  (DTRANK + 2 * DSTATE) // 96
#define NCHUNK  16
#define CLEN    (LLEN / NCHUNK)       // 128

#if defined(__CUDA_ARCH_FEAT_SM103_ALL) || defined(__CUDA_ARCH_FEAT_SM100_ALL)
#define HAS_TCGEN05 1
#else
#define HAS_TCGEN05 0
#endif

typedef __nv_bfloat16 bf16;

// ---------------- scratch ----------------
__device__ bf16  g_u_hi [MTOT * DMODEL];
__device__ bf16  g_u_lo [MTOT * DMODEL];
__device__ float g_xzT  [2 * DINNER * MTOT];   // transposed [ch][m]
__device__ float g_xcT  [DINNER * MTOT];       // transposed [ch][m]
__device__ bf16  g_xc_hi[MTOT * DINNER];
__device__ bf16  g_xc_lo[MTOT * DINNER];
__device__ float g_xdbl [MTOT * XDBL_W];
__device__ bf16  g_dtin_hi[MTOT * DTRANK];
__device__ bf16  g_dtin_lo[MTOT * DTRANK];
__device__ float g_dtT  [DINNER * MTOT];
__device__ float g_yT   [DINNER * MTOT];
__device__ bf16  g_y_hi [MTOT * DINNER];
__device__ bf16  g_y_lo [MTOT * DINNER];
__device__ bf16  g_out_hi[MTOT * DMODEL];
__device__ bf16  g_out_lo[MTOT * DMODEL];
// chunked-scan intermediates
__device__ float g_sA [BB * NCHUNK * DINNER * DSTATE];
__device__ float g_sB [BB * NCHUNK * DINNER * DSTATE];
__device__ float g_h0 [BB * NCHUNK * DINNER * DSTATE];
// weight splits (x_proj padded to 128 rows, head padded to 32256)
__device__ bf16  g_wip_hi[2 * DINNER * DMODEL];
__device__ bf16  g_wip_lo[2 * DINNER * DMODEL];
__device__ bf16  g_wxp_hi[128 * DINNER];
__device__ bf16  g_wxp_lo[128 * DINNER];
__device__ bf16  g_wdt_hi[DINNER * DTRANK];
__device__ bf16  g_wdt_lo[DINNER * DTRANK];
__device__ bf16  g_wop_hi[DMODEL * DINNER];
__device__ bf16  g_wop_lo[DMODEL * DINNER];
__device__ bf16  g_whd_hi[NVPAD * DMODEL];
__device__ bf16  g_whd_lo[NVPAD * DMODEL];

// ---------------- helpers ----------------
__device__ __forceinline__ uint32_t smem_u32(const void* p) {
    uint32_t r;
    asm("{ .reg .u64 t; cvta.to.shared.u64 t, %1; cvt.u32.u64 %0, t; }" : "=r"(r) : "l"(p));
    return r;
}

// SW64 swizzle on byte offsets (64B rows; atom = 8 rows x 64B)
#define SW64(b) ((b) ^ (((b) >> 3) & 0x30))

// 8KB blocks of [128 rows x 32 k] bf16, SW64 inside each block. kblocks = K/32.
__device__ __forceinline__ size_t blk_off(int row, int k, int kblocks) {
    uint32_t inner = ((uint32_t)(row & 127) << 6) | ((uint32_t)(k & 31) << 1);
    inner = SW64(inner);
    return ((size_t)(row >> 7) * kblocks + (uint32_t)(k >> 5)) * 8192u + inner;
}

__device__ __forceinline__ float softplus_f(float x) {
    return fmaxf(x, 0.f) + log1pf(expf(-fabsf(x)));
}

__device__ __forceinline__ void split2(float v, bf16& h, bf16& l) {
    h = __float2bfloat16(v);
    l = __float2bfloat16(v - __bfloat162float(h));
}

__device__ __forceinline__ void store_split8(const float* v, bf16* hi, bf16* lo, size_t off) {
    uint4 hv, lv;
    bf16* hb = reinterpret_cast<bf16*>(&hv);
    bf16* lb = reinterpret_cast<bf16*>(&lv);
#pragma unroll
    for (int q = 0; q < 8; q++) split2(v[q], hb[q], lb[q]);
    *reinterpret_cast<uint4*>(reinterpret_cast<char*>(hi) + off) = hv;
    *reinterpret_cast<uint4*>(reinterpret_cast<char*>(lo) + off) = lv;
}

#if HAS_TCGEN05
__device__ __forceinline__ uint32_t elect1() {
    uint32_t p;
    asm volatile("{\n\t.reg .pred p;\n\telect.sync _|p, 0xFFFFFFFF;\n\tselp.b32 %0, 1, 0, p;\n\t}" : "=r"(p));
    return p;
}

#define MBAR_INIT(addr, cnt) \
    asm volatile("mbarrier.init.shared.b64 [%0], %1;" :: "r"(addr), "r"(cnt) : "memory")

#define MBAR_EXPECT_TX(addr, bytes) \
    asm volatile("mbarrier.arrive.expect_tx.shared.b64 _, [%0], %1;" :: "r"(addr), "r"(bytes) : "memory")

__device__ __forceinline__ void mbar_wait(uint32_t mbar, uint32_t parity) {
    asm volatile("{\n\t.reg .pred P;\n"
                 "W%=:\n\tmbarrier.try_wait.parity.acquire.cta.shared::cta.b64 P, [%0], %1, 0x989680;\n"
                 "\t@!P bra W%=;\n\t}"
                 :: "r"(mbar), "r"(parity) : "memory");
}

__device__ __forceinline__ void bulk_g2s(uint32_t dst, const void* src, uint32_t bytes, uint32_t mbar) {
    asm volatile("cp.async.bulk.shared::cluster.global.mbarrier::complete_tx::bytes [%0], [%1], %2, [%3];"
                 :: "r"(dst), "l"(src), "r"(bytes), "r"(mbar) : "memory");
}

#define TC_COMMIT(mbar) \
    asm volatile("tcgen05.commit.cta_group::1.mbarrier::arrive::one.shared::cluster.b64 [%0];" \
                 :: "r"(mbar) : "memory")

// SMEM descriptor: SW64 (layout 4), version 1, SBO=32, LBO=1
__device__ __forceinline__ uint64_t smem_desc64(uint32_t addr) {
    return 0x8000402000010000ull | ((uint64_t)(addr >> 4) & 0x3FFF);
}

__device__ __forceinline__ void mma_bf16(uint32_t d, uint64_t ad, uint64_t bd,
                                         uint32_t idesc, uint32_t en) {
    asm volatile("{\n\t.reg .pred p;\n\tsetp.ne.u32 p, %5, 0;\n"
                 "\ttcgen05.mma.cta_group::1.kind::f16 [%0], %1, %2, %3, {%4, %4, %4, %4}, p;\n\t}"
                 :: "r"(d), "l"(ad), "l"(bd), "r"(idesc), "r"(0u), "r"(en) : "memory");
}

#define LDTM_X32(r, addr) \
    asm volatile( \
        "tcgen05.ld.sync.aligned.32x32b.x32.b32 " \
        "{%0, %1, %2, %3, %4, %5, %6, %7, " \
        " %8, %9, %10, %11, %12, %13, %14, %15, " \
        " %16, %17, %18, %19, %20, %21, %22, %23, " \
        " %24, %25, %26, %27, %28, %29, %30, %31}, [%32];" \
        : "=r"((r)[0]),  "=r"((r)[1]),  "=r"((r)[2]),  "=r"((r)[3]), \
          "=r"((r)[4]),  "=r"((r)[5]),  "=r"((r)[6]),  "=r"((r)[7]), \
          "=r"((r)[8]),  "=r"((r)[9]),  "=r"((r)[10]), "=r"((r)[11]), \
          "=r"((r)[12]), "=r"((r)[13]), "=r"((r)[14]), "=r"((r)[15]), \
          "=r"((r)[16]), "=r"((r)[17]), "=r"((r)[18]), "=r"((r)[19]), \
          "=r"((r)[20]), "=r"((r)[21]), "=r"((r)[22]), "=r"((r)[23]), \
          "=r"((r)[24]), "=r"((r)[25]), "=r"((r)[26]), "=r"((r)[27]), \
          "=r"((r)[28]), "=r"((r)[29]), "=r"((r)[30]), "=r"((r)[31]) \
        : "r"(addr))
#endif // HAS_TCGEN05

// ---------------- producer kernels (SW64-blocked hi/lo) ----------------
__global__ void split_w_kernel(const float* __restrict__ W,
                               bf16* __restrict__ hi, bf16* __restrict__ lo,
                               int N, int K)
{
    int unit = blockIdx.x * blockDim.x + threadIdx.x;
    int upr = K >> 3;
    int n = unit / upr;
    int kg = (unit - n * upr) << 3;
    float v[8];
    if (n < N) {
        float4 a = *reinterpret_cast<const float4*>(W + (size_t)n * K + kg);
        float4 b = *reinterpret_cast<const float4*>(W + (size_t)n * K + kg + 4);
        v[0]=a.x; v[1]=a.y; v[2]=a.z; v[3]=a.w; v[4]=b.x; v[5]=b.y; v[6]=b.z; v[7]=b.w;
    } else {
#pragma unroll
        for (int q = 0; q < 8; q++) v[q] = 0.f;
    }
    store_split8(v, hi, lo, blk_off(n, kg, K >> 5));
}

__global__ void embed_kernel(const int* __restrict__ tokens,
                             const float* __restrict__ emb,
                             bf16* __restrict__ uhi, bf16* __restrict__ ulo)
{
    int m = blockIdx.x;
    int t = tokens[m];
    const float* src = emb + (size_t)t * DMODEL;
    int kg = threadIdx.x << 3;
    float v[8];
    float4 a = *reinterpret_cast<const float4*>(src + kg);
    float4 b = *reinterpret_cast<const float4*>(src + kg + 4);
    v[0]=a.x; v[1]=a.y; v[2]=a.z; v[3]=a.w; v[4]=b.x; v[5]=b.y; v[6]=b.z; v[7]=b.w;
    store_split8(v, uhi, ulo, blk_off(m, kg, DMODEL >> 5));
}

// transpose [ch][m] fp32 -> blocked hi/lo [m][k=ch]
__global__ void tsplit_kernel(const float* __restrict__ srcT,
                              bf16* __restrict__ hi, bf16* __restrict__ lo,
                              int CHN)
{
    __shared__ float tile[64][129];
    int m0 = blockIdx.x * 128;
    int c0 = blockIdx.y * 64;
    int tid = threadIdx.x;
    for (int u = tid; u < 64 * 128; u += 256) {
        int i = u >> 7, j = u & 127;
        tile[i][j] = srcT[(size_t)(c0 + i) * MTOT + m0 + j];
    }
    __syncthreads();
    int kblocks = CHN >> 5;
    for (int u = tid; u < 1024; u += 256) {
        int mm = u >> 3;
        int kg = (u & 7) << 3;
        float v[8];
#pragma unroll
        for (int q = 0; q < 8; q++) v[q] = tile[kg + q][mm];
        store_split8(v, hi, lo, blk_off(m0 + mm, c0 + kg, kblocks));
    }
}

// ============ GEMM, BN=512 (2x N=256 MMA into 512-col TMEM), K32 chunks, NS=2, 1 CTA/SM ============
// C[M,N] = (Ah+Al)[M,K] * (Wh+Wl)[N,K]^T
// EPI: 1 row-major +bias, 3 split-output blocked, 4 transposed fp32, 5 transposed softplus(+bias)
#define BN5       512
#define NS5       2
#define STAGE5    81920                       // Ah 8K | Al 8K | Bh 32K | Bl 32K
#define GEMM_SMEM_512 (2048 + NS5 * STAGE5)   // 165888
#define IDESC5 ((1u << 4) | (1u << 7) | (1u << 10) | (32u << 17) | (8u << 24))  // N=256 per MMA

template <int EPI>
__global__ __launch_bounds__(256, 1)
void gemm512(const bf16* __restrict__ Ah, const bf16* __restrict__ Al,
             const bf16* __restrict__ Wh, const bf16* __restrict__ Wl,
             const float* __restrict__ bias,
             float* __restrict__ C, bf16* __restrict__ Chi, bf16* __restrict__ Clo,
             int ldc, int N, int K)
{
    extern __shared__ __align__(1024) char smc[];
    uint32_t sbase = smem_u32(smc);
    uint32_t bufs  = (sbase + 1024 + 1023) & ~1023u;

    int tid  = threadIdx.x;
    int wid  = tid >> 5;
    int lane = tid & 31;
    int tileM = blockIdx.x * 128;
    int tileN = blockIdx.y * BN5;
    int CH = K >> 5;

#if HAS_TCGEN05
    const uint32_t TMEM_PTR = sbase;
    #define FULLB(s)  (sbase + 16 + (s) * 8)
    #define EMPTYB(s) (sbase + 48 + (s) * 8)
    #define DONEB     (sbase + 80)

    if (wid == 0) {
        asm volatile("tcgen05.alloc.cta_group::1.sync.aligned.shared::cta.b32 [%0], %1;"
                     :: "r"(TMEM_PTR), "r"((uint32_t)BN5) : "memory");
        asm volatile("tcgen05.relinquish_alloc_permit.cta_group::1.sync.aligned;");
    }
    if (tid == 0) {
        for (int s = 0; s < NS5; s++) { MBAR_INIT(FULLB(s), 1); MBAR_INIT(EMPTYB(s), 1); }
        MBAR_INIT(DONEB, 1);
    }
    __syncthreads();
    uint32_t tmem;
    asm volatile("ld.shared.b32 %0, [%1];" : "=r"(tmem) : "r"(TMEM_PTR));

    if (wid == 1 && elect1()) {
        // producer
        int ph = 1, st = 0;
        size_t aBase = (size_t)(tileM >> 7) * CH;
        for (int c = 0; c < CH; c++) {
            mbar_wait(EMPTYB(st), ph);
            MBAR_EXPECT_TX(FULLB(st), (uint32_t)STAGE5);
            uint32_t dst = bufs + st * STAGE5;
            bulk_g2s(dst,        (const char*)Ah + (aBase + c) * 8192, 8192, FULLB(st));
            bulk_g2s(dst + 8192, (const char*)Al + (aBase + c) * 8192, 8192, FULLB(st));
#pragma unroll
            for (int i = 0; i < 4; i++) {
                size_t bOff = ((size_t)((tileN >> 7) + i) * CH + c) * 8192;
                bulk_g2s(dst + 16384 + i * 8192, (const char*)Wh + bOff, 8192, FULLB(st));
                bulk_g2s(dst + 49152 + i * 8192, (const char*)Wl + bOff, 8192, FULLB(st));
            }
            if (++st == NS5) { st = 0; ph ^= 1; }
        }
    } else if (wid == 0 && elect1()) {
        // MMA issuer: 2 K16 steps x 2 N-halves x 3 split terms = 12 MMAs/chunk
        int ph = 0, st = 0;
        for (int c = 0; c < CH; c++) {
            mbar_wait(FULLB(st), ph);
            uint32_t base = bufs + st * STAGE5;
            uint64_t ah = smem_desc64(base);
            uint64_t al = smem_desc64(base + 8192);
#pragma unroll
            for (int ks = 0; ks < 2; ks++) {
#pragma unroll
                for (int t = 0; t < 2; t++) {
                    uint64_t bh = smem_desc64(base + 16384 + t * 16384);
                    uint64_t bl = smem_desc64(base + 49152 + t * 16384);
                    uint32_t d = tmem + t * 256;
                    uint32_t en0 = (c > 0 || ks > 0) ? 1u : 0u;
                    mma_bf16(d, ah + ks * 2, bh + ks * 2, IDESC5, en0);
                    mma_bf16(d, ah + ks * 2, bl + ks * 2, IDESC5, 1u);
                    mma_bf16(d, al + ks * 2, bh + ks * 2, IDESC5, 1u);
                }
            }
            TC_COMMIT(EMPTYB(st));
            if (++st == NS5) { st = 0; ph ^= 1; }
        }
        TC_COMMIT(DONEB);
    }

    mbar_wait(DONEB, 0);
    asm volatile("tcgen05.fence::after_thread_sync;" ::: "memory");

    // epilogue: warp w -> rows (w&3)*32+lane, cols (w>>2)*256 .. +255, in 32-col batches
    {
        constexpr int CSPAN = BN5 / 2;     // 256
        int part = wid & 3;
        int halfsel = wid >> 2;
        int m = tileM + part * 32 + lane;

        for (int bc = 0; bc < CSPAN; bc += 32) {
            uint32_t rr[32];
            LDTM_X32(rr, tmem + halfsel * CSPAN + bc);
            asm volatile("tcgen05.wait::ld.sync.aligned;" ::: "memory");
            int colbase = tileN + halfsel * CSPAN + bc;

            if (EPI == 4 || EPI == 5) {
#pragma unroll
                for (int j = 0; j < 32; j++) {
                    int col = colbase + j;
                    float v = __uint_as_float(rr[j]);
                    if (EPI == 5) v = softplus_f(v + bias[col]);
                    C[(size_t)col * MTOT + m] = v;
                }
            } else if (EPI == 3) {
#pragma unroll
                for (int j = 0; j < 32; j += 8) {
                    float v[8];
#pragma unroll
                    for (int q = 0; q < 8; q++) v[q] = __uint_as_float(rr[j + q]);
                    store_split8(v, Chi, Clo, blk_off(m, colbase + j, N >> 5));
                }
            } else {
                float* crow = C + (size_t)m * ldc;
#pragma unroll
                for (int j = 0; j < 32; j += 4) {
                    int col = colbase + j;
                    if (col < N) {
                        float t0 = __uint_as_float(rr[j + 0]);
                        float t1 = __uint_as_float(rr[j + 1]);
                        float t2 = __uint_as_float(rr[j + 2]);
                        float t3 = __uint_as_float(rr[j + 3]);
                        if (EPI == 1) {
                            t0 += bias[col + 0]; t1 += bias[col + 1];
                            t2 += bias[col + 2]; t3 += bias[col + 3];
                        }
                        float4 o; o.x = t0; o.y = t1; o.z = t2; o.w = t3;
                        *reinterpret_cast<float4*>(crow + col) = o;
                    }
                }
            }
        }
    }
    __syncthreads();
    if (wid == 0) {
        asm volatile("tcgen05.dealloc.cta_group::1.sync.aligned.b32 %0, %1;"
                     :: "r"(tmem), "r"((uint32_t)BN5));
    }
    #undef FULLB
    #undef EMPTYB
    #undef DONEB
#else
    // compile-only fallback
    int kb = K >> 5;
    for (int e = tid; e < 128 * BN5; e += 256) {
        int r = e / BN5, cc = e % BN5;
        int m = tileM + r, n = tileN + cc;
        float acc = 0.f;
        for (int k = 0; k < K; k++) {
            size_t ao = blk_off(m, k, kb), bo = blk_off(n, k, kb);
            float a = __bfloat162float(*(const bf16*)((const char*)Ah + ao)) +
                      __bfloat162float(*(const bf16*)((const char*)Al + ao));
            float b = __bfloat162float(*(const bf16*)((const char*)Wh + bo)) +
                      __bfloat162float(*(const bf16*)((const char*)Wl + bo));
            acc = fmaf(a, b, acc);
        }
        if (EPI == 1 && n < N) acc += bias[n];
        if (EPI == 5) acc = softplus_f(acc + bias[n]);
        if (EPI == 3) {
            bf16 h, l; split2(acc, h, l);
            size_t off = blk_off(m, n, N >> 5);
            *(bf16*)((char*)Chi + off) = h;
            *(bf16*)((char*)Clo + off) = l;
        } else if (EPI == 4 || EPI == 5) {
            C[(size_t)n * MTOT + m] = acc;
        } else if (n < N) {
            C[(size_t)m * ldc + n] = acc;
        }
    }
#endif
}

// ============ non-cluster GEMM, BN=128, K32 chunks, NS=3 (x_proj, fused dtin split) ============
#define STAGE1 32768
#define GEMM_SMEM_128 (2048 + 3 * STAGE1)
#define IDESC1 ((1u << 4) | (1u << 7) | (1u << 10) | (16u << 17) | (8u << 24))

__global__ __launch_bounds__(256, 1)
void gemm_128(const bf16* __restrict__ Ah, const bf16* __restrict__ Al,
              const bf16* __restrict__ Wh, const bf16* __restrict__ Wl,
              float* __restrict__ C,                 // xdbl row-major (cols 64..95 used)
              bf16* __restrict__ Dh, bf16* __restrict__ Dl,   // blocked dtin (cols 0..63)
              int ldc, int N, int K)
{
    extern __shared__ __align__(1024) char smc[];
    uint32_t sbase = smem_u32(smc);
    uint32_t bufs  = (sbase + 1024 + 1023) & ~1023u;

    int tid  = threadIdx.x;
    int wid  = tid >> 5;
    int lane = tid & 31;
    int tileM = blockIdx.x * 128;
    int CH = K >> 5;

#if HAS_TCGEN05
    const uint32_t TMEM_PTR = sbase;
    #define FULLB(s)  (sbase + 16 + (s) * 8)
    #define EMPTYB(s) (sbase + 48 + (s) * 8)
    #define DONEB     (sbase + 80)

    if (wid == 0) {
        asm volatile("tcgen05.alloc.cta_group::1.sync.aligned.shared::cta.b32 [%0], %1;"
                     :: "r"(TMEM_PTR), "r"(128u) : "memory");
        asm volatile("tcgen05.relinquish_alloc_permit.cta_group::1.sync.aligned;");
    }
    if (tid == 0) {
        for (int s = 0; s < 3; s++) { MBAR_INIT(FULLB(s), 1); MBAR_INIT(EMPTYB(s), 1); }
        MBAR_INIT(DONEB, 1);
    }
    __syncthreads();
    uint32_t tmem;
    asm volatile("ld.shared.b32 %0, [%1];" : "=r"(tmem) : "r"(TMEM_PTR));

    if (wid == 1 && elect1()) {
        int ph = 1, st = 0;
        size_t aBase = (size_t)(tileM >> 7) * CH;
        for (int c = 0; c < CH; c++) {
            mbar_wait(EMPTYB(st), ph);
            MBAR_EXPECT_TX(FULLB(st), (uint32_t)STAGE1);
            uint32_t dst = bufs + st * STAGE1;
            bulk_g2s(dst,         (const char*)Ah + (aBase + c) * 8192, 8192, FULLB(st));
            bulk_g2s(dst + 8192,  (const char*)Al + (aBase + c) * 8192, 8192, FULLB(st));
            bulk_g2s(dst + 16384, (const char*)Wh + (size_t)c * 8192, 8192, FULLB(st));
            bulk_g2s(dst + 24576, (const char*)Wl + (size_t)c * 8192, 8192, FULLB(st));
            if (++st == 3) { st = 0; ph ^= 1; }
        }
    } else if (wid == 0 && elect1()) {
        int ph = 0, st = 0;
        for (int c = 0; c < CH; c++) {
            mbar_wait(FULLB(st), ph);
            uint32_t base = bufs + st * STAGE1;
            uint64_t ah = smem_desc64(base);
            uint64_t al = smem_desc64(base + 8192);
            uint64_t bh = smem_desc64(base + 16384);
            uint64_t bl = smem_desc64(base + 24576);
#pragma unroll
            for (int ks = 0; ks < 2; ks++) {
                uint32_t en0 = (c > 0 || ks > 0) ? 1u : 0u;
                mma_bf16(tmem, ah + ks * 2, bh + ks * 2, IDESC1, en0);
                mma_bf16(tmem, ah + ks * 2, bl + ks * 2, IDESC1, 1u);
                mma_bf16(tmem, al + ks * 2, bh + ks * 2, IDESC1, 1u);
            }
            TC_COMMIT(EMPTYB(st));
            if (++st == 3) { st = 0; ph ^= 1; }
        }
        TC_COMMIT(DONEB);
    }

    mbar_wait(DONEB, 0);
    asm volatile("tcgen05.fence::after_thread_sync;" ::: "memory");

    {
        int part = wid & 3;
        int halfsel = wid >> 2;
        int m = tileM + part * 32 + lane;
        for (int bc = 0; bc < 64; bc += 32) {
            uint32_t rr[32];
            LDTM_X32(rr, tmem + halfsel * 64 + bc);
            asm volatile("tcgen05.wait::ld.sync.aligned;" ::: "memory");
            int colbase = halfsel * 64 + bc;

            if (halfsel == 0) {
                // cols 0..63 = dt input -> blocked hi/lo (kblocks = 2)
#pragma unroll
                for (int j = 0; j < 32; j += 8) {
                    float v[8];
#pragma unroll
                    for (int q = 0; q < 8; q++) v[q] = __uint_as_float(rr[j + q]);
                    store_split8(v, Dh, Dl, blk_off(m, colbase + j, 2));
                }
            } else {
                // cols 64..127: write fp32 xdbl for cols 64..95 (B, C)
                float* crow = C + (size_t)m * ldc;
#pragma unroll
                for (int j = 0; j < 32; j += 4) {
                    int col = colbase + j;
                    if (col < N) {
                        float4 o;
                        o.x = __uint_as_float(rr[j + 0]);
                        o.y = __uint_as_float(rr[j + 1]);
                        o.z = __uint_as_float(rr[j + 2]);
                        o.w = __uint_as_float(rr[j + 3]);
                        *reinterpret_cast<float4*>(crow + col) = o;
                    }
                }
            }
        }
    }
    __syncthreads();
    if (wid == 0) {
        asm volatile("tcgen05.dealloc.cta_group::1.sync.aligned.b32 %0, %1;"
                     :: "r"(tmem), "r"(128u));
    }
    #undef FULLB
    #undef EMPTYB
    #undef DONEB
#else
    int kb = K >> 5;
    for (int e = tid; e < 128 * 128; e += 256) {
        int r = e >> 7, cc = e & 127;
        int m = tileM + r, n = cc;
        float acc = 0.f;
        for (int k = 0; k < K; k++) {
            size_t ao = blk_off(m, k, kb), bo = blk_off(n, k, kb);
            float a = __bfloat162float(*(const bf16*)((const char*)Ah + ao)) +
                      __bfloat162float(*(const bf16*)((const char*)Al + ao));
            float b = __bfloat162float(*(const bf16*)((const char*)Wh + bo)) +
                      __bfloat162float(*(const bf16*)((const char*)Wl + bo));
            acc = fmaf(a, b, acc);
        }
        if (n < 64) {
            bf16 h, l; split2(acc, h, l);
            size_t off = blk_off(m, n, 2);
            *(bf16*)((char*)Dh + off) = h;
            *(bf16*)((char*)Dl + off) = l;
        } else if (n < N) {
            C[(size_t)m * ldc + n] = acc;
        }
    }
#endif
}

// ---------------- causal depthwise conv (K=4) + SiLU, transposed layout --------
__global__ void conv_silu_kernel(const float* __restrict__ xzT,
                                 const float* __restrict__ conv_w,
                                 const float* __restrict__ conv_b,
                                 float* __restrict__ xcT)
{
    int d = blockIdx.y;
    int m = blockIdx.x * 256 + threadIdx.x;
    int l = m & (LLEN - 1);
    const float* xs = xzT + (size_t)d * MTOT;
    float acc = conv_b[d];
#pragma unroll
    for (int k = 0; k < 4; k++) {
        int off = k - 3;
        if (l + off >= 0)
            acc = fmaf(xs[m + off], conv_w[d * 4 + k], acc);
    }
    xcT[(size_t)d * MTOT + m] = acc / (1.f + __expf(-acc));
}

// ================= chunked parallel selective scan (NCHUNK=16) =================
__global__ __launch_bounds__(128)
void scan_phaseA(const float* __restrict__ xcT,
                 const float* __restrict__ xdbl,
                 const float* __restrict__ dtT,
                 const float* __restrict__ A_log,
                 float* __restrict__ sA, float* __restrict__ sB)
{
    int lane = threadIdx.x & 31;
    int warp = threadIdx.x >> 5;
    int s    = lane & 15;
    int half = lane >> 4;
    int bx   = blockIdx.x;
    int blkc = bx % 256;
    int c    = (bx / 256) % (NCHUNK - 1);   // chunks 0..14
    int b    = bx / (256 * (NCHUNK - 1));
    int d    = blkc * 8 + warp * 2 + half;

    float Aval = -expf(A_log[d * DSTATE + s]);
    int l0 = c * CLEN;

    const float* dts = dtT + (size_t)d * MTOT + b * LLEN + l0;
    const float* xcs = xcT + (size_t)d * MTOT + b * LLEN + l0;
    const float* bcp = xdbl + (size_t)(b * LLEN + l0) * XDBL_W + DTRANK + s;

    float ap = 1.f, hp = 0.f;
    for (int i = 0; i < CLEN; i += 4) {
        float4 dt4 = *reinterpret_cast<const float4*>(dts + i);
        float4 xc4 = *reinterpret_cast<const float4*>(xcs + i);
        float dtv[4] = {dt4.x, dt4.y, dt4.z, dt4.w};
        float xv [4] = {xc4.x, xc4.y, xc4.z, xc4.w};
#pragma unroll
        for (int j = 0; j < 4; j++) {
            float Bv = bcp[(size_t)(i + j) * XDBL_W];
            float a = __expf(dtv[j] * Aval);
            ap *= a;
            hp = fmaf(a, hp, dtv[j] * Bv * xv[j]);
        }
    }
    size_t o = ((size_t)(b * NCHUNK + c) * DINNER + d) * DSTATE + s;
    sA[o] = ap;
    sB[o] = hp;
}

__global__ void scan_phaseB(const float* __restrict__ sA,
                            const float* __restrict__ sB,
                            float* __restrict__ h0)
{
    int idx = blockIdx.x * blockDim.x + threadIdx.x;   // BB*DINNER*DSTATE
    int b = idx / (DINNER * DSTATE);
    int r = idx - b * DINNER * DSTATE;
    float h = 0.f;
#pragma unroll
    for (int c = 0; c < NCHUNK; c++) {
        size_t o = ((size_t)(b * NCHUNK + c) * DINNER * DSTATE) + r;
        h0[o] = h;
        if (c < NCHUNK - 1)
            h = fmaf(sA[o], h, sB[o]);
    }
}

__global__ __launch_bounds__(128)
void scan_phaseC(const float* __restrict__ xzT,
                 const float* __restrict__ xcT,
                 const float* __restrict__ xdbl,
                 const float* __restrict__ dtT,
                 const float* __restrict__ A_log,
                 const float* __restrict__ Dv,
                 const float* __restrict__ h0,
                 float* __restrict__ yT)
{
    int lane = threadIdx.x & 31;
    int warp = threadIdx.x >> 5;
    int s    = lane & 15;
    int half = lane >> 4;
    int bx   = blockIdx.x;
    int blkc = bx & 255;
    int c    = (bx >> 8) & (NCHUNK - 1);
    int b    = bx >> 12;
    int d    = blkc * 8 + warp * 2 + half;

    float Aval = -expf(A_log[d * DSTATE + s]);
    float Dd   = Dv[d];
    int l0 = c * CLEN;

    const float* dts = dtT + (size_t)d * MTOT + b * LLEN + l0;
    const float* xcs = xcT + (size_t)d * MTOT + b * LLEN + l0;
    const float* zs  = xzT + (size_t)(DINNER + d) * MTOT + b * LLEN + l0;
    float*       ys  = yT  + (size_t)d * MTOT + b * LLEN + l0;
    const float* bcp = xdbl + (size_t)(b * LLEN + l0) * XDBL_W + DTRANK + s;

    float h = h0[((size_t)(b * NCHUNK + c) * DINNER + d) * DSTATE + s];

    for (int i = 0; i < CLEN; i += 4) {
        float4 dt4 = *reinterpret_cast<const float4*>(dts + i);
        float4 xc4 = *reinterpret_cast<const float4*>(xcs + i);
        float4 z4  = *reinterpret_cast<const float4*>(zs + i);
        float dtv[4] = {dt4.x, dt4.y, dt4.z, dt4.w};
        float xv [4] = {xc4.x, xc4.y, xc4.z, xc4.w};
        float zv [4] = {z4.x, z4.y, z4.z, z4.w};
#pragma unroll
        for (int j = 0; j < 4; j++) {
            float Bv = bcp[(size_t)(i + j) * XDBL_W];
            float Cv = bcp[(size_t)(i + j) * XDBL_W + DSTATE];
            h = fmaf(__expf(dtv[j] * Aval), h, dtv[j] * Bv * xv[j]);
            float p = h * Cv;
            p += __shfl_xor_sync(0xffffffffu, p, 8);
            p += __shfl_xor_sync(0xffffffffu, p, 4);
            p += __shfl_xor_sync(0xffffffffu, p, 2);
            p += __shfl_xor_sync(0xffffffffu, p, 1);
            if (s == 0) {
                float z = zv[j];
                float sz = z / (1.f + __expf(-z));
                ys[i + j] = (p + Dd * xv[j]) * sz;
            }
        }
    }
}

// ---------------- launcher ----------------
extern "C" void kernel_launch(void* const* d_in, const int* in_sizes, int n_in,
                              void* d_out, int out_size)
{
    const int*   tokens    = (const int*)  d_in[0];
    const float* emb       = (const float*)d_in[1];
    const float* in_proj_w = (const float*)d_in[2];
    const float* conv_w    = (const float*)d_in[3];
    const float* conv_b    = (const float*)d_in[4];
    const float* x_proj_w  = (const float*)d_in[5];
    const float* dt_proj_w = (const float*)d_in[6];
    const float* dt_proj_b = (const float*)d_in[7];
    const float* A_log     = (const float*)d_in[8];
    const float* Dv        = (const float*)d_in[9];
    const float* out_proj_w= (const float*)d_in[10];
    const float* head_w    = (const float*)d_in[11];
    const float* head_b    = (const float*)d_in[12];
    float* logits = (float*)d_out;

    bf16 *uh, *ul, *xch, *xcl, *dih, *dil, *yh, *yl, *oh, *ol;
    bf16 *wiph, *wipl, *wxph, *wxpl, *wdth, *wdtl, *woph, *wopl, *whdh, *whdl;
    float *pxzT, *pxcT, *pxdbl, *pdtT, *pyT, *psA, *psB, *ph0;
    cudaGetSymbolAddress((void**)&uh,   g_u_hi);   cudaGetSymbolAddress((void**)&ul,   g_u_lo);
    cudaGetSymbolAddress((void**)&pxzT, g_xzT);
    cudaGetSymbolAddress((void**)&pxcT, g_xcT);
    cudaGetSymbolAddress((void**)&xch,  g_xc_hi);  cudaGetSymbolAddress((void**)&xcl,  g_xc_lo);
    cudaGetSymbolAddress((void**)&pxdbl,g_xdbl);
    cudaGetSymbolAddress((void**)&dih,  g_dtin_hi);cudaGetSymbolAddress((void**)&dil,  g_dtin_lo);
    cudaGetSymbolAddress((void**)&pdtT, g_dtT);
    cudaGetSymbolAddress((void**)&pyT,  g_yT);
    cudaGetSymbolAddress((void**)&psA,  g_sA);
    cudaGetSymbolAddress((void**)&psB,  g_sB);
    cudaGetSymbolAddress((void**)&ph0,  g_h0);
    cudaGetSymbolAddress((void**)&yh,   g_y_hi);   cudaGetSymbolAddress((void**)&yl,   g_y_lo);
    cudaGetSymbolAddress((void**)&oh,   g_out_hi); cudaGetSymbolAddress((void**)&ol,   g_out_lo);
    cudaGetSymbolAddress((void**)&wiph, g_wip_hi); cudaGetSymbolAddress((void**)&wipl, g_wip_lo);
    cudaGetSymbolAddress((void**)&wxph, g_wxp_hi); cudaGetSymbolAddress((void**)&wxpl, g_wxp_lo);
    cudaGetSymbolAddress((void**)&wdth, g_wdt_hi); cudaGetSymbolAddress((void**)&wdtl, g_wdt_lo);
    cudaGetSymbolAddress((void**)&woph, g_wop_hi); cudaGetSymbolAddress((void**)&wopl, g_wop_lo);
    cudaGetSymbolAddress((void**)&whdh, g_whd_hi); cudaGetSymbolAddress((void**)&whdl, g_whd_lo);

    cudaFuncSetAttribute(gemm512<1>, cudaFuncAttributeMaxDynamicSharedMemorySize, GEMM_SMEM_512);
    cudaFuncSetAttribute(gemm512<3>, cudaFuncAttributeMaxDynamicSharedMemorySize, GEMM_SMEM_512);
    cudaFuncSetAttribute(gemm512<4>, cudaFuncAttributeMaxDynamicSharedMemorySize, GEMM_SMEM_512);
    cudaFuncSetAttribute(gemm512<5>, cudaFuncAttributeMaxDynamicSharedMemorySize, GEMM_SMEM_512);
    cudaFuncSetAttribute(gemm_128,   cudaFuncAttributeMaxDynamicSharedMemorySize, GEMM_SMEM_128);

    // 0: embedding gather + split
    embed_kernel<<<MTOT, 128>>>(tokens, emb, uh, ul);
    // 1: in_proj weight split
    split_w_kernel<<<(4096 * 1024 / 8) / 256, 256>>>(in_proj_w, wiph, wipl, 4096, 1024);
    // 2: x_proj weight split
    split_w_kernel<<<(128 * 2048 / 8) / 256, 256>>>(x_proj_w, wxph, wxpl, 96, 2048);

    // 3: in_proj GEMM (profile slot): xzT[4096 ch][4096 m]
    gemm512<4><<<dim3(MTOT / 128, 4096 / 512), 256, GEMM_SMEM_512>>>(
        uh, ul, wiph, wipl, nullptr, pxzT, nullptr, nullptr, 0, 4096, 1024);

    // 4: causal depthwise conv + silu (transposed) -> xcT
    conv_silu_kernel<<<dim3(MTOT / 256, DINNER), 256>>>(pxzT, conv_w, conv_b, pxcT);

    // 5: xcT -> blocked xc hi/lo
    tsplit_kernel<<<dim3(MTOT / 128, DINNER / 64), 256>>>(pxcT, xch, xcl, DINNER);

    // 6: x_proj GEMM with fused dtin split (cols 0..63 -> blocked, 64..95 -> xdbl)
    gemm_128<<<dim3(MTOT / 128, 1), 256, GEMM_SMEM_128>>>(
        xch, xcl, wxph, wxpl, pxdbl, dih, dil, XDBL_W, XDBL_W, 2048);

    // 7: dt weight split
    split_w_kernel<<<(2048 * 64 / 8) / 256, 256>>>(dt_proj_w, wdth, wdtl, 2048, 64);

    // 8: dt = softplus(dtin @ dt_proj_w^T + b), stored transposed dtT[ch][m]
    gemm512<5><<<dim3(MTOT / 128, 2048 / 512), 256, GEMM_SMEM_512>>>(
        dih, dil, wdth, wdtl, dt_proj_b, pdtT, nullptr, nullptr, 0, 2048, 64);

    // 9-11: chunked parallel scan
    scan_phaseA<<<BB * (NCHUNK - 1) * 256, 128>>>(pxcT, pxdbl, pdtT, A_log, psA, psB);
    scan_phaseB<<<(BB * DINNER * DSTATE) / 256, 256>>>(psA, psB, ph0);
    scan_phaseC<<<BB * NCHUNK * 256, 128>>>(pxzT, pxcT, pxdbl, pdtT, A_log, Dv, ph0, pyT);

    // 12: yT -> blocked y hi/lo
    tsplit_kernel<<<dim3(MTOT / 128, DINNER / 64), 256>>>(pyT, yh, yl, DINNER);

    // 13: out_proj weight split
    split_w_kernel<<<(1024 * 2048 / 8) / 256, 256>>>(out_proj_w, woph, wopl, 1024, 2048);

    // 14: out_proj (blocked split output)
    gemm512<3><<<dim3(MTOT / 128, 1024 / 512), 256, GEMM_SMEM_512>>>(
        yh, yl, woph, wopl, nullptr, nullptr, oh, ol, 1024, 1024, 2048);

    // 15: head weight split (padded rows zeroed)
    split_w_kernel<<<((size_t)NVPAD * 1024 / 8) / 256, 256>>>(head_w, whdh, whdl, 32000, 1024);

    // 16: head GEMM (bf16 3-term, N padded to 32256)
    gemm512<1><<<dim3(MTOT / 128, NVPAD / 512), 256, GEMM_SMEM_512>>>(
        oh, ol, whdh, whdl, head_b, logits, nullptr, nullptr, 32000, 32000, 1024);
}

// round 14
// speedup vs baseline: 1.0789x; 1.0789x over previous
#include <cuda_runtime.h>
#include <cuda_bf16.h>
#include <math.h>
#include <stdint.h>

// ---------------- problem constants ----------------
#define BB      2
#define LLEN    2048
#define DMODEL  1024
#define DINNER  2048
#define DSTATE  16
#define DTRANK  64
#define NVOCAB  32000
#define MTOT    (BB * LLEN)           // 4096 rows
#define XDBL_W  (DTRANK + 2 * DSTATE) // 96
#define NCHUNK  16
#define CLEN    (LLEN / NCHUNK)       // 128

#if defined(__CUDA_ARCH_FEAT_SM103_ALL) || defined(__CUDA_ARCH_FEAT_SM100_ALL)
#define HAS_TCGEN05 1
#else
#define HAS_TCGEN05 0
#endif

typedef __nv_bfloat16 bf16;

// ---------------- scratch ----------------
__device__ bf16  g_u_hi [MTOT * DMODEL];
__device__ bf16  g_u_lo [MTOT * DMODEL];
__device__ float g_xzT  [2 * DINNER * MTOT];   // transposed [ch][m]
__device__ float g_xcT  [DINNER * MTOT];       // transposed [ch][m]
__device__ bf16  g_xc_hi[MTOT * DINNER];
__device__ bf16  g_xc_lo[MTOT * DINNER];
__device__ float g_xdbl [MTOT * XDBL_W];
__device__ bf16  g_dtin_hi[MTOT * DTRANK];
__device__ bf16  g_dtin_lo[MTOT * DTRANK];
__device__ float g_dtT  [DINNER * MTOT];
__device__ float g_yT   [DINNER * MTOT];
__device__ bf16  g_y_hi [MTOT * DINNER];
__device__ bf16  g_y_lo [MTOT * DINNER];
__device__ bf16  g_out_hi[MTOT * DMODEL];
__device__ bf16  g_out_lo[MTOT * DMODEL];
// chunked-scan intermediates
__device__ float g_sA [BB * NCHUNK * DINNER * DSTATE];
__device__ float g_sB [BB * NCHUNK * DINNER * DSTATE];
__device__ float g_h0 [BB * NCHUNK * DINNER * DSTATE];
// weight splits (x_proj padded to 128 rows)
__device__ bf16  g_wip_hi[2 * DINNER * DMODEL];
__device__ bf16  g_wip_lo[2 * DINNER * DMODEL];
__device__ bf16  g_wxp_hi[128 * DINNER];
__device__ bf16  g_wxp_lo[128 * DINNER];
__device__ bf16  g_wdt_hi[DINNER * DTRANK];
__device__ bf16  g_wdt_lo[DINNER * DTRANK];
__device__ bf16  g_wop_hi[DMODEL * DINNER];
__device__ bf16  g_wop_lo[DMODEL * DINNER];
__device__ bf16  g_whd_hi[NVOCAB * DMODEL];
__device__ bf16  g_whd_lo[NVOCAB * DMODEL];

// ---------------- helpers ----------------
__device__ __forceinline__ uint32_t smem_u32(const void* p) {
    uint32_t r;
    asm("{ .reg .u64 t; cvta.to.shared.u64 t, %1; cvt.u32.u64 %0, t; }" : "=r"(r) : "l"(p));
    return r;
}

// SW64 swizzle on byte offsets (64B rows; atom = 8 rows x 64B)
#define SW64(b) ((b) ^ (((b) >> 3) & 0x30))

// 8KB blocks of [128 rows x 32 k] bf16, SW64 inside each block. kblocks = K/32.
__device__ __forceinline__ size_t blk_off(int row, int k, int kblocks) {
    uint32_t inner = ((uint32_t)(row & 127) << 6) | ((uint32_t)(k & 31) << 1);
    inner = SW64(inner);
    return ((size_t)(row >> 7) * kblocks + (uint32_t)(k >> 5)) * 8192u + inner;
}

__device__ __forceinline__ float softplus_f(float x) {
    return fmaxf(x, 0.f) + log1pf(expf(-fabsf(x)));
}

__device__ __forceinline__ void split2(float v, bf16& h, bf16& l) {
    h = __float2bfloat16(v);
    l = __float2bfloat16(v - __bfloat162float(h));
}

__device__ __forceinline__ void store_split8(const float* v, bf16* hi, bf16* lo, size_t off) {
    uint4 hv, lv;
    bf16* hb = reinterpret_cast<bf16*>(&hv);
    bf16* lb = reinterpret_cast<bf16*>(&lv);
#pragma unroll
    for (int q = 0; q < 8; q++) split2(v[q], hb[q], lb[q]);
    *reinterpret_cast<uint4*>(reinterpret_cast<char*>(hi) + off) = hv;
    *reinterpret_cast<uint4*>(reinterpret_cast<char*>(lo) + off) = lv;
}

#if HAS_TCGEN05
__device__ __forceinline__ uint32_t elect1() {
    uint32_t p;
    asm volatile("{\n\t.reg .pred p;\n\telect.sync _|p, 0xFFFFFFFF;\n\tselp.b32 %0, 1, 0, p;\n\t}" : "=r"(p));
    return p;
}

#define MBAR_INIT(addr, cnt) \
    asm volatile("mbarrier.init.shared.b64 [%0], %1;" :: "r"(addr), "r"(cnt) : "memory")

#define MBAR_EXPECT_TX(addr, bytes) \
    asm volatile("mbarrier.arrive.expect_tx.shared.b64 _, [%0], %1;" :: "r"(addr), "r"(bytes) : "memory")

__device__ __forceinline__ void mbar_wait(uint32_t mbar, uint32_t parity) {
    asm volatile("{\n\t.reg .pred P;\n"
                 "W%=:\n\tmbarrier.try_wait.parity.acquire.cta.shared::cta.b64 P, [%0], %1, 0x989680;\n"
                 "\t@!P bra W%=;\n\t}"
                 :: "r"(mbar), "r"(parity) : "memory");
}

__device__ __forceinline__ void bulk_g2s(uint32_t dst, const void* src, uint32_t bytes, uint32_t mbar) {
    asm volatile("cp.async.bulk.shared::cluster.global.mbarrier::complete_tx::bytes [%0], [%1], %2, [%3];"
                 :: "r"(dst), "l"(src), "r"(bytes), "r"(mbar) : "memory");
}

#define TC_COMMIT(mbar) \
    asm volatile("tcgen05.commit.cta_group::1.mbarrier::arrive::one.shared::cluster.b64 [%0];" \
                 :: "r"(mbar) : "memory")

// SMEM descriptor: SW64 (layout 4), version 1, SBO=32, LBO=1
__device__ __forceinline__ uint64_t smem_desc64(uint32_t addr) {
    return 0x8000402000010000ull | ((uint64_t)(addr >> 4) & 0x3FFF);
}

__device__ __forceinline__ void mma_bf16(uint32_t d, uint64_t ad, uint64_t bd,
                                         uint32_t idesc, uint32_t en) {
    asm volatile("{\n\t.reg .pred p;\n\tsetp.ne.u32 p, %5, 0;\n"
                 "\ttcgen05.mma.cta_group::1.kind::f16 [%0], %1, %2, %3, {%4, %4, %4, %4}, p;\n\t}"
                 :: "r"(d), "l"(ad), "l"(bd), "r"(idesc), "r"(0u), "r"(en) : "memory");
}

#define LDTM_X32(r, addr) \
    asm volatile( \
        "tcgen05.ld.sync.aligned.32x32b.x32.b32 " \
        "{%0, %1, %2, %3, %4, %5, %6, %7, " \
        " %8, %9, %10, %11, %12, %13, %14, %15, " \
        " %16, %17, %18, %19, %20, %21, %22, %23, " \
        " %24, %25, %26, %27, %28, %29, %30, %31}, [%32];" \
        : "=r"((r)[0]),  "=r"((r)[1]),  "=r"((r)[2]),  "=r"((r)[3]), \
          "=r"((r)[4]),  "=r"((r)[5]),  "=r"((r)[6]),  "=r"((r)[7]), \
          "=r"((r)[8]),  "=r"((r)[9]),  "=r"((r)[10]), "=r"((r)[11]), \
          "=r"((r)[12]), "=r"((r)[13]), "=r"((r)[14]), "=r"((r)[15]), \
          "=r"((r)[16]), "=r"((r)[17]), "=r"((r)[18]), "=r"((r)[19]), \
          "=r"((r)[20]), "=r"((r)[21]), "=r"((r)[22]), "=r"((r)[23]), \
          "=r"((r)[24]), "=r"((r)[25]), "=r"((r)[26]), "=r"((r)[27]), \
          "=r"((r)[28]), "=r"((r)[29]), "=r"((r)[30]), "=r"((r)[31]) \
        : "r"(addr))
#endif // HAS_TCGEN05

// ---------------- producer kernels (SW64-blocked hi/lo) ----------------
__global__ void split_w_kernel(const float* __restrict__ W,
                               bf16* __restrict__ hi, bf16* __restrict__ lo,
                               int N, int K)
{
    int unit = blockIdx.x * blockDim.x + threadIdx.x;
    int upr = K >> 3;
    int n = unit / upr;
    int kg = (unit - n * upr) << 3;
    float v[8];
    if (n < N) {
        float4 a = *reinterpret_cast<const float4*>(W + (size_t)n * K + kg);
        float4 b = *reinterpret_cast<const float4*>(W + (size_t)n * K + kg + 4);
        v[0]=a.x; v[1]=a.y; v[2]=a.z; v[3]=a.w; v[4]=b.x; v[5]=b.y; v[6]=b.z; v[7]=b.w;
    } else {
#pragma unroll
        for (int q = 0; q < 8; q++) v[q] = 0.f;
    }
    store_split8(v, hi, lo, blk_off(n, kg, K >> 5));
}

__global__ void embed_kernel(const int* __restrict__ tokens,
                             const float* __restrict__ emb,
                             bf16* __restrict__ uhi, bf16* __restrict__ ulo)
{
    int m = blockIdx.x;
    int t = tokens[m];
    const float* src = emb + (size_t)t * DMODEL;
    int kg = threadIdx.x << 3;
    float v[8];
    float4 a = *reinterpret_cast<const float4*>(src + kg);
    float4 b = *reinterpret_cast<const float4*>(src + kg + 4);
    v[0]=a.x; v[1]=a.y; v[2]=a.z; v[3]=a.w; v[4]=b.x; v[5]=b.y; v[6]=b.z; v[7]=b.w;
    store_split8(v, uhi, ulo, blk_off(m, kg, DMODEL >> 5));
}

// transpose [ch][m] fp32 -> blocked hi/lo [m][k=ch]
__global__ void tsplit_kernel(const float* __restrict__ srcT,
                              bf16* __restrict__ hi, bf16* __restrict__ lo,
                              int CHN)
{
    __shared__ float tile[64][129];
    int m0 = blockIdx.x * 128;
    int c0 = blockIdx.y * 64;
    int tid = threadIdx.x;
    for (int u = tid; u < 64 * 128; u += 256) {
        int i = u >> 7, j = u & 127;
        tile[i][j] = srcT[(size_t)(c0 + i) * MTOT + m0 + j];
    }
    __syncthreads();
    int kblocks = CHN >> 5;
    for (int u = tid; u < 1024; u += 256) {
        int mm = u >> 3;
        int kg = (u & 7) << 3;
        float v[8];
#pragma unroll
        for (int q = 0; q < 8; q++) v[q] = tile[kg + q][mm];
        store_split8(v, hi, lo, blk_off(m0 + mm, c0 + kg, kblocks));
    }
}

// ============ GEMM, BN=256, K32 chunks, NS=2, 2 CTAs/SM ============
// EPI: 1 row-major +bias, 4 transposed fp32, 5 transposed softplus(+bias)
#define BN2       256
#define NS2       2
#define STAGE2    49152                       // Ah 8K | Al 8K | Bh 16K | Bl 16K
#define GEMM_SMEM_256 (2048 + NS2 * STAGE2)   // 100352
#define IDESC2 ((1u << 4) | (1u << 7) | (1u << 10) | ((BN2 / 8u) << 17) | (8u << 24))

template <int EPI>
__global__ __launch_bounds__(256, 2)
void gemm_tc(const bf16* __restrict__ Ah, const bf16* __restrict__ Al,
             const bf16* __restrict__ Wh, const bf16* __restrict__ Wl,
             const float* __restrict__ bias,
             float* __restrict__ C, int ldc, int N, int K)
{
    extern __shared__ __align__(1024) char smc[];
    uint32_t sbase = smem_u32(smc);
    uint32_t bufs  = (sbase + 1024 + 1023) & ~1023u;

    int tid  = threadIdx.x;
    int wid  = tid >> 5;
    int lane = tid & 31;
    int tileM = blockIdx.x * 128;
    int tileN = blockIdx.y * BN2;
    int CH = K >> 5;

#if HAS_TCGEN05
    const uint32_t TMEM_PTR = sbase;
    #define FULLB(s)  (sbase + 16 + (s) * 8)
    #define EMPTYB(s) (sbase + 48 + (s) * 8)
    #define DONEB     (sbase + 80)

    if (wid == 0) {
        asm volatile("tcgen05.alloc.cta_group::1.sync.aligned.shared::cta.b32 [%0], %1;"
                     :: "r"(TMEM_PTR), "r"((uint32_t)BN2) : "memory");
        asm volatile("tcgen05.relinquish_alloc_permit.cta_group::1.sync.aligned;");
    }
    if (tid == 0) {
        for (int s = 0; s < NS2; s++) { MBAR_INIT(FULLB(s), 1); MBAR_INIT(EMPTYB(s), 1); }
        MBAR_INIT(DONEB, 1);
    }
    __syncthreads();
    uint32_t tmem;
    asm volatile("ld.shared.b32 %0, [%1];" : "=r"(tmem) : "r"(TMEM_PTR));

    if (wid == 1 && elect1()) {
        int ph = 1, st = 0;
        size_t aBase = (size_t)(tileM >> 7) * CH;
        for (int c = 0; c < CH; c++) {
            mbar_wait(EMPTYB(st), ph);
            MBAR_EXPECT_TX(FULLB(st), (uint32_t)STAGE2);
            uint32_t dst = bufs + st * STAGE2;
            bulk_g2s(dst,        (const char*)Ah + (aBase + c) * 8192, 8192, FULLB(st));
            bulk_g2s(dst + 8192, (const char*)Al + (aBase + c) * 8192, 8192, FULLB(st));
#pragma unroll
            for (int i = 0; i < 2; i++) {
                size_t bOff = ((size_t)((tileN >> 7) + i) * CH + c) * 8192;
                bulk_g2s(dst + 16384 + i * 8192, (const char*)Wh + bOff, 8192, FULLB(st));
                bulk_g2s(dst + 32768 + i * 8192, (const char*)Wl + bOff, 8192, FULLB(st));
            }
            if (++st == NS2) { st = 0; ph ^= 1; }
        }
    } else if (wid == 0 && elect1()) {
        int ph = 0, st = 0;
        for (int c = 0; c < CH; c++) {
            mbar_wait(FULLB(st), ph);
            uint32_t base = bufs + st * STAGE2;
            uint64_t ah = smem_desc64(base);
            uint64_t al = smem_desc64(base + 8192);
            uint64_t bh = smem_desc64(base + 16384);
            uint64_t bl = smem_desc64(base + 32768);
#pragma unroll
            for (int ks = 0; ks < 2; ks++) {
                uint32_t en0 = (c > 0 || ks > 0) ? 1u : 0u;
                mma_bf16(tmem, ah + ks * 2, bh + ks * 2, IDESC2, en0);
                mma_bf16(tmem, ah + ks * 2, bl + ks * 2, IDESC2, 1u);
                mma_bf16(tmem, al + ks * 2, bh + ks * 2, IDESC2, 1u);
            }
            TC_COMMIT(EMPTYB(st));
            if (++st == NS2) { st = 0; ph ^= 1; }
        }
        TC_COMMIT(DONEB);
    }

    mbar_wait(DONEB, 0);
    asm volatile("tcgen05.fence::after_thread_sync;" ::: "memory");

    {
        constexpr int CSPAN = BN2 / 2;
        int part = wid & 3;
        int halfsel = wid >> 2;
        int m = tileM + part * 32 + lane;

        for (int bc = 0; bc < CSPAN; bc += 32) {
            uint32_t rr[32];
            LDTM_X32(rr, tmem + halfsel * CSPAN + bc);
            asm volatile("tcgen05.wait::ld.sync.aligned;" ::: "memory");
            int colbase = tileN + halfsel * CSPAN + bc;

            if (EPI == 4 || EPI == 5) {
#pragma unroll
                for (int j = 0; j < 32; j++) {
                    int col = colbase + j;
                    float v = __uint_as_float(rr[j]);
                    if (EPI == 5) v = softplus_f(v + bias[col]);
                    C[(size_t)col * MTOT + m] = v;
                }
            } else {
                float* crow = C + (size_t)m * ldc;
#pragma unroll
                for (int j = 0; j < 32; j += 4) {
                    int col = colbase + j;
                    if (col < N) {
                        float t0 = __uint_as_float(rr[j + 0]);
                        float t1 = __uint_as_float(rr[j + 1]);
                        float t2 = __uint_as_float(rr[j + 2]);
                        float t3 = __uint_as_float(rr[j + 3]);
                        if (EPI == 1) {
                            t0 += bias[col + 0]; t1 += bias[col + 1];
                            t2 += bias[col + 2]; t3 += bias[col + 3];
                        }
                        float4 o; o.x = t0; o.y = t1; o.z = t2; o.w = t3;
                        *reinterpret_cast<float4*>(crow + col) = o;
                    }
                }
            }
        }
    }
    __syncthreads();
    if (wid == 0) {
        asm volatile("tcgen05.dealloc.cta_group::1.sync.aligned.b32 %0, %1;"
                     :: "r"(tmem), "r"((uint32_t)BN2));
    }
    #undef FULLB
    #undef EMPTYB
    #undef DONEB
#else
    int kb = K >> 5;
    for (int e = tid; e < 128 * BN2; e += 256) {
        int r = e / BN2, cc = e % BN2;
        int m = tileM + r, n = tileN + cc;
        float acc = 0.f;
        for (int k = 0; k < K; k++) {
            size_t ao = blk_off(m, k, kb), bo = blk_off(n, k, kb);
            float a = __bfloat162float(*(const bf16*)((const char*)Ah + ao)) +
                      __bfloat162float(*(const bf16*)((const char*)Al + ao));
            float b = __bfloat162float(*(const bf16*)((const char*)Wh + bo)) +
                      __bfloat162float(*(const bf16*)((const char*)Wl + bo));
            acc = fmaf(a, b, acc);
        }
        if (EPI == 1 && n < N) { C[(size_t)m * ldc + n] = acc + bias[n]; }
        else if (EPI == 5) C[(size_t)n * MTOT + m] = softplus_f(acc + bias[n]);
        else if (EPI == 4) C[(size_t)n * MTOT + m] = acc;
    }
#endif
}

// ============ BN=128 GEMM, K32 chunks, NS=3, 2 CTAs/SM ============
// EPI 7: x_proj fused (cols 0..63 -> blocked dtin hi/lo, 64..95 -> fp32 xdbl)
// EPI 3: blocked split output (out_proj)
#define STAGE1 32768
#define GEMM_SMEM_128 (2048 + 3 * STAGE1)
#define IDESC1 ((1u << 4) | (1u << 7) | (1u << 10) | (16u << 17) | (8u << 24))

template <int EPI>
__global__ __launch_bounds__(256, 2)
void gemm128(const bf16* __restrict__ Ah, const bf16* __restrict__ Al,
             const bf16* __restrict__ Wh, const bf16* __restrict__ Wl,
             float* __restrict__ C,
             bf16* __restrict__ Dh, bf16* __restrict__ Dl,
             int ldc, int N, int K)
{
    extern __shared__ __align__(1024) char smc[];
    uint32_t sbase = smem_u32(smc);
    uint32_t bufs  = (sbase + 1024 + 1023) & ~1023u;

    int tid  = threadIdx.x;
    int wid  = tid >> 5;
    int lane = tid & 31;
    int tileM = blockIdx.x * 128;
    int tileN = blockIdx.y * 128;
    int CH = K >> 5;

#if HAS_TCGEN05
    const uint32_t TMEM_PTR = sbase;
    #define FULLB(s)  (sbase + 16 + (s) * 8)
    #define EMPTYB(s) (sbase + 48 + (s) * 8)
    #define DONEB     (sbase + 80)

    if (wid == 0) {
        asm volatile("tcgen05.alloc.cta_group::1.sync.aligned.shared::cta.b32 [%0], %1;"
                     :: "r"(TMEM_PTR), "r"(128u) : "memory");
        asm volatile("tcgen05.relinquish_alloc_permit.cta_group::1.sync.aligned;");
    }
    if (tid == 0) {
        for (int s = 0; s < 3; s++) { MBAR_INIT(FULLB(s), 1); MBAR_INIT(EMPTYB(s), 1); }
        MBAR_INIT(DONEB, 1);
    }
    __syncthreads();
    uint32_t tmem;
    asm volatile("ld.shared.b32 %0, [%1];" : "=r"(tmem) : "r"(TMEM_PTR));

    if (wid == 1 && elect1()) {
        int ph = 1, st = 0;
        size_t aBase = (size_t)(tileM >> 7) * CH;
        size_t bBase = (size_t)(tileN >> 7) * CH;
        for (int c = 0; c < CH; c++) {
            mbar_wait(EMPTYB(st), ph);
            MBAR_EXPECT_TX(FULLB(st), (uint32_t)STAGE1);
            uint32_t dst = bufs + st * STAGE1;
            bulk_g2s(dst,         (const char*)Ah + (aBase + c) * 8192, 8192, FULLB(st));
            bulk_g2s(dst + 8192,  (const char*)Al + (aBase + c) * 8192, 8192, FULLB(st));
            bulk_g2s(dst + 16384, (const char*)Wh + (bBase + c) * 8192, 8192, FULLB(st));
            bulk_g2s(dst + 24576, (const char*)Wl + (bBase + c) * 8192, 8192, FULLB(st));
            if (++st == 3) { st = 0; ph ^= 1; }
        }
    } else if (wid == 0 && elect1()) {
        int ph = 0, st = 0;
        for (int c = 0; c < CH; c++) {
            mbar_wait(FULLB(st), ph);
            uint32_t base = bufs + st * STAGE1;
            uint64_t ah = smem_desc64(base);
            uint64_t al = smem_desc64(base + 8192);
            uint64_t bh = smem_desc64(base + 16384);
            uint64_t bl = smem_desc64(base + 24576);
#pragma unroll
            for (int ks = 0; ks < 2; ks++) {
                uint32_t en0 = (c > 0 || ks > 0) ? 1u : 0u;
                mma_bf16(tmem, ah + ks * 2, bh + ks * 2, IDESC1, en0);
                mma_bf16(tmem, ah + ks * 2, bl + ks * 2, IDESC1, 1u);
                mma_bf16(tmem, al + ks * 2, bh + ks * 2, IDESC1, 1u);
            }
            TC_COMMIT(EMPTYB(st));
            if (++st == 3) { st = 0; ph ^= 1; }
        }
        TC_COMMIT(DONEB);
    }

    mbar_wait(DONEB, 0);
    asm volatile("tcgen05.fence::after_thread_sync;" ::: "memory");

    {
        int part = wid & 3;
        int halfsel = wid >> 2;
        int m = tileM + part * 32 + lane;
        for (int bc = 0; bc < 64; bc += 32) {
            uint32_t rr[32];
            LDTM_X32(rr, tmem + halfsel * 64 + bc);
            asm volatile("tcgen05.wait::ld.sync.aligned;" ::: "memory");
            int colbase = halfsel * 64 + bc;

            if (EPI == 7) {
                if (halfsel == 0) {
                    // cols 0..63 = dt input -> blocked hi/lo (kblocks = 2)
#pragma unroll
                    for (int j = 0; j < 32; j += 8) {
                        float v[8];
#pragma unroll
                        for (int q = 0; q < 8; q++) v[q] = __uint_as_float(rr[j + q]);
                        store_split8(v, Dh, Dl, blk_off(m, colbase + j, 2));
                    }
                } else {
                    // cols 64..127: write fp32 xdbl for cols 64..95
                    float* crow = C + (size_t)m * ldc;
#pragma unroll
                    for (int j = 0; j < 32; j += 4) {
                        int col = colbase + j;
                        if (col < N) {
                            float4 o;
                            o.x = __uint_as_float(rr[j + 0]);
                            o.y = __uint_as_float(rr[j + 1]);
                            o.z = __uint_as_float(rr[j + 2]);
                            o.w = __uint_as_float(rr[j + 3]);
                            *reinterpret_cast<float4*>(crow + col) = o;
                        }
                    }
                }
            } else {   // EPI == 3: blocked split output
#pragma unroll
                for (int j = 0; j < 32; j += 8) {
                    float v[8];
#pragma unroll
                    for (int q = 0; q < 8; q++) v[q] = __uint_as_float(rr[j + q]);
                    store_split8(v, Dh, Dl, blk_off(m, tileN + colbase + j, N >> 5));
                }
            }
        }
    }
    __syncthreads();
    if (wid == 0) {
        asm volatile("tcgen05.dealloc.cta_group::1.sync.aligned.b32 %0, %1;"
                     :: "r"(tmem), "r"(128u));
    }
    #undef FULLB
    #undef EMPTYB
    #undef DONEB
#else
    int kb = K >> 5;
    for (int e = tid; e < 128 * 128; e += 256) {
        int r = e >> 7, cc = e & 127;
        int m = tileM + r, n = tileN + cc;
        float acc = 0.f;
        for (int k = 0; k < K; k++) {
            size_t ao = blk_off(m, k, kb), bo = blk_off(n, k, kb);
            float a = __bfloat162float(*(const bf16*)((const char*)Ah + ao)) +
                      __bfloat162float(*(const bf16*)((const char*)Al + ao));
            float b = __bfloat162float(*(const bf16*)((const char*)Wh + bo)) +
                      __bfloat162float(*(const bf16*)((const char*)Wl + bo));
            acc = fmaf(a, b, acc);
        }
        if (EPI == 7) {
            if (n < 64) {
                bf16 h, l; split2(acc, h, l);
                size_t off = blk_off(m, n, 2);
                *(bf16*)((char*)Dh + off) = h;
                *(bf16*)((char*)Dl + off) = l;
            } else if (n < N) {
                C[(size_t)m * ldc + n] = acc;
            }
        } else {
            bf16 h, l; split2(acc, h, l);
            size_t off = blk_off(m, n, N >> 5);
            *(bf16*)((char*)Dh + off) = h;
            *(bf16*)((char*)Dl + off) = l;
        }
    }
#endif
}

// ---------------- causal depthwise conv (K=4) + SiLU, transposed layout --------
__global__ void conv_silu_kernel(const float* __restrict__ xzT,
                                 const float* __restrict__ conv_w,
                                 const float* __restrict__ conv_b,
                                 float* __restrict__ xcT)
{
    int d = blockIdx.y;
    int m = blockIdx.x * 256 + threadIdx.x;
    int l = m & (LLEN - 1);
    const float* xs = xzT + (size_t)d * MTOT;
    float acc = conv_b[d];
#pragma unroll
    for (int k = 0; k < 4; k++) {
        int off = k - 3;
        if (l + off >= 0)
            acc = fmaf(xs[m + off], conv_w[d * 4 + k], acc);
    }
    xcT[(size_t)d * MTOT + m] = acc / (1.f + __expf(-acc));
}

// ================= chunked parallel selective scan (NCHUNK=16) =================
__global__ __launch_bounds__(128)
void scan_phaseA(const float* __restrict__ xcT,
                 const float* __restrict__ xdbl,
                 const float* __restrict__ dtT,
                 const float* __restrict__ A_log,
                 float* __restrict__ sA, float* __restrict__ sB)
{
    int lane = threadIdx.x & 31;
    int warp = threadIdx.x >> 5;
    int s    = lane & 15;
    int half = lane >> 4;
    int bx   = blockIdx.x;
    int blkc = bx % 256;
    int c    = (bx / 256) % (NCHUNK - 1);
    int b    = bx / (256 * (NCHUNK - 1));
    int d    = blkc * 8 + warp * 2 + half;

    float Aval = -expf(A_log[d * DSTATE + s]);
    int l0 = c * CLEN;

    const float* dts = dtT + (size_t)d * MTOT + b * LLEN + l0;
    const float* xcs = xcT + (size_t)d * MTOT + b * LLEN + l0;
    const float* bcp = xdbl + (size_t)(b * LLEN + l0) * XDBL_W + DTRANK + s;

    float ap = 1.f, hp = 0.f;
    for (int i = 0; i < CLEN; i += 4) {
        float4 dt4 = *reinterpret_cast<const float4*>(dts + i);
        float4 xc4 = *reinterpret_cast<const float4*>(xcs + i);
        float dtv[4] = {dt4.x, dt4.y, dt4.z, dt4.w};
        float xv [4] = {xc4.x, xc4.y, xc4.z, xc4.w};
#pragma unroll
        for (int j = 0; j < 4; j++) {
            float Bv = bcp[(size_t)(i + j) * XDBL_W];
            float a = __expf(dtv[j] * Aval);
            ap *= a;
            hp = fmaf(a, hp, dtv[j] * Bv * xv[j]);
        }
    }
    size_t o = ((size_t)(b * NCHUNK + c) * DINNER + d) * DSTATE + s;
    sA[o] = ap;
    sB[o] = hp;
}

__global__ void scan_phaseB(const float* __restrict__ sA,
                            const float* __restrict__ sB,
                            float* __restrict__ h0)
{
    int idx = blockIdx.x * blockDim.x + threadIdx.x;
    int b = idx / (DINNER * DSTATE);
    int r = idx - b * DINNER * DSTATE;
    float h = 0.f;
#pragma unroll
    for (int c = 0; c < NCHUNK; c++) {
        size_t o = ((size_t)(b * NCHUNK + c) * DINNER * DSTATE) + r;
        h0[o] = h;
        if (c < NCHUNK - 1)
            h = fmaf(sA[o], h, sB[o]);
    }
}

__global__ __launch_bounds__(128)
void scan_phaseC(const float* __restrict__ xzT,
                 const float* __restrict__ xcT,
                 const float* __restrict__ xdbl,
                 const float* __restrict__ dtT,
                 const float* __restrict__ A_log,
                 const float* __restrict__ Dv,
                 const float* __restrict__ h0,
                 float* __restrict__ yT)
{
    int lane = threadIdx.x & 31;
    int warp = threadIdx.x >> 5;
    int s    = lane & 15;
    int half = lane >> 4;
    int bx   = blockIdx.x;
    int blkc = bx & 255;
    int c    = (bx >> 8) & (NCHUNK - 1);
    int b    = bx >> 12;
    int d    = blkc * 8 + warp * 2 + half;

    float Aval = -expf(A_log[d * DSTATE + s]);
    float Dd   = Dv[d];
    int l0 = c * CLEN;

    const float* dts = dtT + (size_t)d * MTOT + b * LLEN + l0;
    const float* xcs = xcT + (size_t)d * MTOT + b * LLEN + l0;
    const float* zs  = xzT + (size_t)(DINNER + d) * MTOT + b * LLEN + l0;
    float*       ys  = yT  + (size_t)d * MTOT + b * LLEN + l0;
    const float* bcp = xdbl + (size_t)(b * LLEN + l0) * XDBL_W + DTRANK + s;

    float h = h0[((size_t)(b * NCHUNK + c) * DINNER + d) * DSTATE + s];

    for (int i = 0; i < CLEN; i += 4) {
        float4 dt4 = *reinterpret_cast<const float4*>(dts + i);
        float4 xc4 = *reinterpret_cast<const float4*>(xcs + i);
        float4 z4  = *reinterpret_cast<const float4*>(zs + i);
        float dtv[4] = {dt4.x, dt4.y, dt4.z, dt4.w};
        float xv [4] = {xc4.x, xc4.y, xc4.z, xc4.w};
        float zv [4] = {z4.x, z4.y, z4.z, z4.w};
#pragma unroll
        for (int j = 0; j < 4; j++) {
            float Bv = bcp[(size_t)(i + j) * XDBL_W];
            float Cv = bcp[(size_t)(i + j) * XDBL_W + DSTATE];
            h = fmaf(__expf(dtv[j] * Aval), h, dtv[j] * Bv * xv[j]);
            float p = h * Cv;
            p += __shfl_xor_sync(0xffffffffu, p, 8);
            p += __shfl_xor_sync(0xffffffffu, p, 4);
            p += __shfl_xor_sync(0xffffffffu, p, 2);
            p += __shfl_xor_sync(0xffffffffu, p, 1);
            if (s == 0) {
                float z = zv[j];
                float sz = z / (1.f + __expf(-z));
                ys[i + j] = (p + Dd * xv[j]) * sz;
            }
        }
    }
}

// ---------------- launcher ----------------
extern "C" void kernel_launch(void* const* d_in, const int* in_sizes, int n_in,
                              void* d_out, int out_size)
{
    const int*   tokens    = (const int*)  d_in[0];
    const float* emb       = (const float*)d_in[1];
    const float* in_proj_w = (const float*)d_in[2];
    const float* conv_w    = (const float*)d_in[3];
    const float* conv_b    = (const float*)d_in[4];
    const float* x_proj_w  = (const float*)d_in[5];
    const float* dt_proj_w = (const float*)d_in[6];
    const float* dt_proj_b = (const float*)d_in[7];
    const float* A_log     = (const float*)d_in[8];
    const float* Dv        = (const float*)d_in[9];
    const float* out_proj_w= (const float*)d_in[10];
    const float* head_w    = (const float*)d_in[11];
    const float* head_b    = (const float*)d_in[12];
    float* logits = (float*)d_out;

    bf16 *uh, *ul, *xch, *xcl, *dih, *dil, *yh, *yl, *oh, *ol;
    bf16 *wiph, *wipl, *wxph, *wxpl, *wdth, *wdtl, *woph, *wopl, *whdh, *whdl;
    float *pxzT, *pxcT, *pxdbl, *pdtT, *pyT, *psA, *psB, *ph0;
    cudaGetSymbolAddress((void**)&uh,   g_u_hi);   cudaGetSymbolAddress((void**)&ul,   g_u_lo);
    cudaGetSymbolAddress((void**)&pxzT, g_xzT);
    cudaGetSymbolAddress((void**)&pxcT, g_xcT);
    cudaGetSymbolAddress((void**)&xch,  g_xc_hi);  cudaGetSymbolAddress((void**)&xcl,  g_xc_lo);
    cudaGetSymbolAddress((void**)&pxdbl,g_xdbl);
    cudaGetSymbolAddress((void**)&dih,  g_dtin_hi);cudaGetSymbolAddress((void**)&dil,  g_dtin_lo);
    cudaGetSymbolAddress((void**)&pdtT, g_dtT);
    cudaGetSymbolAddress((void**)&pyT,  g_yT);
    cudaGetSymbolAddress((void**)&psA,  g_sA);
    cudaGetSymbolAddress((void**)&psB,  g_sB);
    cudaGetSymbolAddress((void**)&ph0,  g_h0);
    cudaGetSymbolAddress((void**)&yh,   g_y_hi);   cudaGetSymbolAddress((void**)&yl,   g_y_lo);
    cudaGetSymbolAddress((void**)&oh,   g_out_hi); cudaGetSymbolAddress((void**)&ol,   g_out_lo);
    cudaGetSymbolAddress((void**)&wiph, g_wip_hi); cudaGetSymbolAddress((void**)&wipl, g_wip_lo);
    cudaGetSymbolAddress((void**)&wxph, g_wxp_hi); cudaGetSymbolAddress((void**)&wxpl, g_wxp_lo);
    cudaGetSymbolAddress((void**)&wdth, g_wdt_hi); cudaGetSymbolAddress((void**)&wdtl, g_wdt_lo);
    cudaGetSymbolAddress((void**)&woph, g_wop_hi); cudaGetSymbolAddress((void**)&wopl, g_wop_lo);
    cudaGetSymbolAddress((void**)&whdh, g_whd_hi); cudaGetSymbolAddress((void**)&whdl, g_whd_lo);

    cudaFuncSetAttribute(gemm_tc<1>, cudaFuncAttributeMaxDynamicSharedMemorySize, GEMM_SMEM_256);
    cudaFuncSetAttribute(gemm_tc<4>, cudaFuncAttributeMaxDynamicSharedMemorySize, GEMM_SMEM_256);
    cudaFuncSetAttribute(gemm_tc<5>, cudaFuncAttributeMaxDynamicSharedMemorySize, GEMM_SMEM_256);
    cudaFuncSetAttribute(gemm128<7>, cudaFuncAttributeMaxDynamicSharedMemorySize, GEMM_SMEM_128);
    cudaFuncSetAttribute(gemm128<3>, cudaFuncAttributeMaxDynamicSharedMemorySize, GEMM_SMEM_128);

    // 0: embedding gather + split
    embed_kernel<<<MTOT, 128>>>(tokens, emb, uh, ul);
    // 1: in_proj weight split
    split_w_kernel<<<(4096 * 1024 / 8) / 256, 256>>>(in_proj_w, wiph, wipl, 4096, 1024);
    // 2: x_proj weight split
    split_w_kernel<<<(128 * 2048 / 8) / 256, 256>>>(x_proj_w, wxph, wxpl, 96, 2048);

    // 3: in_proj GEMM (profile slot): xzT[4096 ch][4096 m]
    gemm_tc<4><<<dim3(MTOT / 128, 4096 / 256), 256, GEMM_SMEM_256>>>(
        uh, ul, wiph, wipl, nullptr, pxzT, 0, 4096, 1024);

    // 4: causal depthwise conv + silu (transposed) -> xcT
    conv_silu_kernel<<<dim3(MTOT / 256, DINNER), 256>>>(pxzT, conv_w, conv_b, pxcT);

    // 5: xcT -> blocked xc hi/lo
    tsplit_kernel<<<dim3(MTOT / 128, DINNER / 64), 256>>>(pxcT, xch, xcl, DINNER);

    // 6: x_proj GEMM with fused dtin split
    gemm128<7><<<dim3(MTOT / 128, 1), 256, GEMM_SMEM_128>>>(
        xch, xcl, wxph, wxpl, pxdbl, dih, dil, XDBL_W, XDBL_W, 2048);

    // 7: dt weight split
    split_w_kernel<<<(2048 * 64 / 8) / 256, 256>>>(dt_proj_w, wdth, wdtl, 2048, 64);

    // 8: dt = softplus(dtin @ dt_proj_w^T + b), transposed dtT[ch][m]
    gemm_tc<5><<<dim3(MTOT / 128, 2048 / 256), 256, GEMM_SMEM_256>>>(
        dih, dil, wdth, wdtl, dt_proj_b, pdtT, 0, 2048, 64);

    // 9-11: chunked parallel scan
    scan_phaseA<<<BB * (NCHUNK - 1) * 256, 128>>>(pxcT, pxdbl, pdtT, A_log, psA, psB);
    scan_phaseB<<<(BB * DINNER * DSTATE) / 256, 256>>>(psA, psB, ph0);
    scan_phaseC<<<BB * NCHUNK * 256, 128>>>(pxzT, pxcT, pxdbl, pdtT, A_log, Dv, ph0, pyT);

    // 12: yT -> blocked y hi/lo
    tsplit_kernel<<<dim3(MTOT / 128, DINNER / 64), 256>>>(pyT, yh, yl, DINNER);

    // 13: out_proj weight split
    split_w_kernel<<<(1024 * 2048 / 8) / 256, 256>>>(out_proj_w, woph, wopl, 1024, 2048);

    // 14: out_proj, BN=128 tiles (256 CTAs -> single 86%-filled wave)
    gemm128<3><<<dim3(MTOT / 128, 1024 / 128), 256, GEMM_SMEM_128>>>(
        yh, yl, woph, wopl, nullptr, oh, ol, 1024, 1024, 2048);

    // 15: head weight split
    split_w_kernel<<<(32000 * 1024 / 8) / 256, 256>>>(head_w, whdh, whdl, 32000, 1024);

    // 16: head GEMM (bf16 3-term)
    gemm_tc<1><<<dim3(MTOT / 128, 32000 / 256), 256, GEMM_SMEM_256>>>(
        oh, ol, whdh, whdl, head_b, logits, 32000, 32000, 1024);
}